// round 2
// baseline (speedup 1.0000x reference)
#include <cuda_runtime.h>

// Shapes (fixed by the problem)
#define B    32
#define C    512
#define HW   3136      // 56*56
#define HW4  784       // HW / 4
#define NROW (B * C)   // 16384
#define KK   3
#define PAD  1

// Scratch (no allocation allowed in kernel_launch)
__device__ float g_y[NROW];     // per-(b,c) mean
__device__ float g_attn[NROW];  // per-(b,c) sigmoid attention

// ---------------------------------------------------------------------------
// Kernel 1: global average pool over H*W. One block per (b,c) row.
// ---------------------------------------------------------------------------
__global__ void __launch_bounds__(256) mean_kernel(const float* __restrict__ x) {
    const int row = blockIdx.x;
    const float4* __restrict__ p =
        reinterpret_cast<const float4*>(x + (size_t)row * HW);

    float s = 0.0f;
    for (int j = threadIdx.x; j < HW4; j += 256) {
        float4 v = p[j];
        s += (v.x + v.y) + (v.z + v.w);
    }

    // warp reduce
    #pragma unroll
    for (int off = 16; off > 0; off >>= 1)
        s += __shfl_xor_sync(0xffffffffu, s, off);

    __shared__ float warp_sums[8];
    const int lane = threadIdx.x & 31;
    const int wid  = threadIdx.x >> 5;
    if (lane == 0) warp_sums[wid] = s;
    __syncthreads();

    if (wid == 0) {
        float t = (lane < 8) ? warp_sums[lane] : 0.0f;
        #pragma unroll
        for (int off = 4; off > 0; off >>= 1)
            t += __shfl_xor_sync(0xffffffffu, t, off);
        if (lane == 0) g_y[row] = t * (1.0f / (float)HW);
    }
}

// ---------------------------------------------------------------------------
// Kernel 2: deformable channel attention. grid = B, block = C.
// Matches reference semantics exactly:
//   offset[k,c] = sum_j w_offset[k,0,j] * y_zeropad[c + j - PAD]
//   pos = c + k - PAD + offset ; p0 = floor(pos) ; frac = pos - p0
//   sample(i) = (0 <= i < C) ? y[i] : 0
//   v = sample(p0)*(1-frac) + sample(p0+1)*frac
//   attn = sigmoid( sum_k w_deform[k]*v + b_deform )
// ---------------------------------------------------------------------------
__global__ void __launch_bounds__(C) attn_kernel(const float* __restrict__ w_offset,
                                                 const float* __restrict__ w_deform,
                                                 const float* __restrict__ b_deform) {
    __shared__ float ys[C];
    const int b = blockIdx.x;
    const int c = threadIdx.x;

    ys[c] = g_y[b * C + c];
    __syncthreads();

    const float ym = (c > 0)     ? ys[c - 1] : 0.0f;
    const float y0 = ys[c];
    const float yp = (c < C - 1) ? ys[c + 1] : 0.0f;

    float acc = b_deform[0];
    #pragma unroll
    for (int k = 0; k < KK; ++k) {
        const float off = w_offset[k * KK + 0] * ym
                        + w_offset[k * KK + 1] * y0
                        + w_offset[k * KK + 2] * yp;
        const float pos  = (float)(c + k - PAD) + off;
        const float p0f  = floorf(pos);
        const float frac = pos - p0f;
        const int   i0   = (int)p0f;
        const int   i1   = i0 + 1;
        const float s0 = (i0 >= 0 && i0 < C) ? ys[i0] : 0.0f;
        const float s1 = (i1 >= 0 && i1 < C) ? ys[i1] : 0.0f;
        acc += w_deform[k] * (s0 * (1.0f - frac) + s1 * frac);
    }

    g_attn[b * C + c] = 1.0f / (1.0f + __expf(-acc));
}

// ---------------------------------------------------------------------------
// Kernel 3: out = attn[b,c] * x. One block per (b,c) row, float4 streaming.
// ---------------------------------------------------------------------------
__global__ void __launch_bounds__(256) scale_kernel(const float* __restrict__ x,
                                                    float* __restrict__ out) {
    const int row = blockIdx.x;
    const float a = g_attn[row];
    const float4* __restrict__ p =
        reinterpret_cast<const float4*>(x + (size_t)row * HW);
    float4* __restrict__ q =
        reinterpret_cast<float4*>(out + (size_t)row * HW);

    for (int j = threadIdx.x; j < HW4; j += 256) {
        float4 v = p[j];
        v.x *= a; v.y *= a; v.z *= a; v.w *= a;
        q[j] = v;
    }
}

// ---------------------------------------------------------------------------
extern "C" void kernel_launch(void* const* d_in, const int* in_sizes, int n_in,
                              void* d_out, int out_size) {
    const float* x        = (const float*)d_in[0];
    const float* w_offset = (const float*)d_in[1];
    const float* w_deform = (const float*)d_in[2];
    const float* b_deform = (const float*)d_in[3];
    float* out = (float*)d_out;

    mean_kernel<<<NROW, 256>>>(x);
    attn_kernel<<<B, C>>>(w_offset, w_deform, b_deform);
    scale_kernel<<<NROW, 256>>>(x, out);
}

// round 6
// speedup vs baseline: 1.0978x; 1.0978x over previous
#include <cuda_runtime.h>

// Shapes (fixed by the problem)
#define B    32
#define C    512
#define HW   3136      // 56*56
#define HW4  784       // HW / 4 float4 per row
#define NROW (B * C)   // 16384
#define KK   3
#define PAD  1

// Scratch (no allocation allowed in kernel_launch)
__device__ float g_y[NROW];     // per-(b,c) mean

// ---------------------------------------------------------------------------
// Kernel 1: global average pool. One WARP per (b,c) row -> deep MLP, no BAR.
// grid = NROW/8 = 2048, block = 256 (8 warps).
// 784 float4 per row = 24 full warp-iterations + 16-lane tail.
// ---------------------------------------------------------------------------
__global__ void __launch_bounds__(256) mean_kernel(const float* __restrict__ x) {
    const int lane = threadIdx.x & 31;
    const int wid  = threadIdx.x >> 5;
    const int row  = (blockIdx.x << 3) + wid;

    const float4* __restrict__ p =
        reinterpret_cast<const float4*>(x + (size_t)row * HW);

    float s = 0.0f;
    #pragma unroll 8
    for (int i = 0; i < 24; ++i) {
        float4 v = p[lane + (i << 5)];
        s += (v.x + v.y) + (v.z + v.w);
    }
    if (lane < 16) {
        float4 v = p[768 + lane];
        s += (v.x + v.y) + (v.z + v.w);
    }

    #pragma unroll
    for (int off = 16; off > 0; off >>= 1)
        s += __shfl_xor_sync(0xffffffffu, s, off);

    if (lane == 0) g_y[row] = s * (1.0f / (float)HW);
}

// ---------------------------------------------------------------------------
// Kernel 2: fused attn-compute + scale. One block per (b,c) row.
// Thread 0 computes attn[b,c] from g_y (a dozen L2-hit loads + sigmoid);
// all threads pre-issue their x loads so the attn latency hides underneath.
// Reference semantics:
//   offset[k] = sum_j w_offset[k,0,j] * y_zeropad[c + j - PAD]
//   pos = c + k - PAD + offset ; p0 = floor(pos) ; frac = pos - p0
//   sample(i) = (0 <= i < C) ? y[b,i] : 0
//   v = sample(p0)*(1-frac) + sample(p0+1)*frac
//   attn = sigmoid( sum_k w_deform[k]*v + b_deform )
// ---------------------------------------------------------------------------
__global__ void __launch_bounds__(256) scale_kernel(const float* __restrict__ x,
                                                    const float* __restrict__ w_offset,
                                                    const float* __restrict__ w_deform,
                                                    const float* __restrict__ b_deform,
                                                    float* __restrict__ out) {
    const int row = blockIdx.x;           // row = b*C + c
    const int tid = threadIdx.x;

    const float4* __restrict__ p =
        reinterpret_cast<const float4*>(x + (size_t)row * HW);
    float4* __restrict__ q =
        reinterpret_cast<float4*>(out + (size_t)row * HW);

    // Pre-issue the streaming loads (held in regs across the barrier).
    float4 v0 = p[tid];
    float4 v1 = p[tid + 256];
    float4 v2 = p[tid + 512];
    float4 v3;
    const bool has3 = (tid < HW4 - 768);  // 16 tail elements
    if (has3) v3 = p[tid + 768];

    __shared__ float a_sh;
    if (tid == 0) {
        const int b = row >> 9;           // /C
        const int c = row & (C - 1);      // %C
        const float* __restrict__ yb = g_y + (b << 9);

        const float ym = (c > 0)     ? yb[c - 1] : 0.0f;
        const float y0 = yb[c];
        const float yp = (c < C - 1) ? yb[c + 1] : 0.0f;

        float acc = b_deform[0];
        #pragma unroll
        for (int k = 0; k < KK; ++k) {
            const float off = w_offset[k * KK + 0] * ym
                            + w_offset[k * KK + 1] * y0
                            + w_offset[k * KK + 2] * yp;
            const float pos  = (float)(c + k - PAD) + off;
            const float p0f  = floorf(pos);
            const float frac = pos - p0f;
            const int   i0   = (int)p0f;
            const int   i1   = i0 + 1;
            const float s0 = (i0 >= 0 && i0 < C) ? yb[i0] : 0.0f;
            const float s1 = (i1 >= 0 && i1 < C) ? yb[i1] : 0.0f;
            acc += w_deform[k] * (s0 * (1.0f - frac) + s1 * frac);
        }
        a_sh = 1.0f / (1.0f + __expf(-acc));
    }
    __syncthreads();
    const float a = a_sh;

    v0.x *= a; v0.y *= a; v0.z *= a; v0.w *= a;
    v1.x *= a; v1.y *= a; v1.z *= a; v1.w *= a;
    v2.x *= a; v2.y *= a; v2.z *= a; v2.w *= a;
    q[tid]       = v0;
    q[tid + 256] = v1;
    q[tid + 512] = v2;
    if (has3) {
        v3.x *= a; v3.y *= a; v3.z *= a; v3.w *= a;
        q[tid + 768] = v3;
    }
}

// ---------------------------------------------------------------------------
extern "C" void kernel_launch(void* const* d_in, const int* in_sizes, int n_in,
                              void* d_out, int out_size) {
    const float* x        = (const float*)d_in[0];
    const float* w_offset = (const float*)d_in[1];
    const float* w_deform = (const float*)d_in[2];
    const float* b_deform = (const float*)d_in[3];
    float* out = (float*)d_out;

    mean_kernel<<<NROW / 8, 256>>>(x);
    scale_kernel<<<NROW, 256>>>(x, w_offset, w_deform, b_deform, out);
}